// round 4
// baseline (speedup 1.0000x reference)
#include <cuda_runtime.h>

#define KN 32
#define DF 128
#define TPAD 36   // transposed-tile row stride (floats): 16B-aligned rows, conflict-free maps

// Packed Blackwell FFMA2: c += a*b on f32x2 lanes
__device__ __forceinline__ void fma2(float2& c, float2 a, float2 b) {
    asm("fma.rn.f32x2 %0, %1, %2, %0;"
        : "+l"(*reinterpret_cast<unsigned long long*>(&c))
        : "l"(*reinterpret_cast<unsigned long long*>(&a)),
          "l"(*reinterpret_cast<unsigned long long*>(&b)));
}
__device__ __forceinline__ float2 bcast2(float x) {
    float2 r;
    asm("mov.b64 %0, {%1, %1};"
        : "=l"(*reinterpret_cast<unsigned long long*>(&r)) : "f"(x));
    return r;
}

__global__ void __launch_bounds__(256)
coatt_kernel(const float* __restrict__ feat,
             const int* __restrict__ sim_idx,
             const int* __restrict__ cor_idx,
             float* __restrict__ out)
{
    __shared__ float sDt[DF][TPAD];            // Dm transposed [d][k]
    __shared__ float sQt[DF][TPAD];            // Qm transposed [d][k]
    __shared__ float sL[KN][KN + 1];           // logits (pad 33)
    __shared__ float sCinv[KN], sMc[KN];       // column stats (AS softmax)
    __shared__ float sRs[KN],   sMr[KN];       // row stats (AC softmax)
    __shared__ __align__(16) float sw[KN];
    __shared__ __align__(16) float sv[KN];
    __shared__ float sp_[KN];
    __shared__ int   sIdx[2 * KN];
    __shared__ float sm[3 * DF];

    const int n   = blockIdx.x;
    const int tid = threadIdx.x;

    // ---- neighbor indices ----
    if (tid < 2 * KN)
        sIdx[tid] = (tid < KN) ? sim_idx[n * KN + tid]
                               : cor_idx[n * KN + (tid - KN)];
    __syncthreads();

    // ---- gather: warp w owns d in [16w,16w+16), lane owns neighbor j ----
    // store banks: (TPAD*d + lane) mod 32 = (4d + lane) -> all lanes distinct
    {
        const int w    = tid >> 5;
        const int lane = tid & 31;
        const int d0   = w * 16;
        const float4* rowD = (const float4*)(feat + (size_t)sIdx[lane]      * DF + d0);
        const float4* rowQ = (const float4*)(feat + (size_t)sIdx[KN + lane] * DF + d0);
        #pragma unroll
        for (int c = 0; c < 4; c++) {
            float4 vD = __ldg(rowD + c);
            float4 vQ = __ldg(rowQ + c);
            const int d = d0 + 4 * c;
            sDt[d + 0][lane] = vD.x; sDt[d + 1][lane] = vD.y;
            sDt[d + 2][lane] = vD.z; sDt[d + 3][lane] = vD.w;
            sQt[d + 0][lane] = vQ.x; sQt[d + 1][lane] = vQ.y;
            sQt[d + 2][lane] = vQ.z; sQt[d + 3][lane] = vQ.w;
        }
    }
    __syncthreads();

    // ---- L = Dm @ Qm^T: split-d halves, 4k x 2j tiles, packed FFMA2 ----
    const int half = tid >> 7;             // d-half: 0 -> [0,64), 1 -> [64,128)
    const int t7   = tid & 127;
    const int kk   = (t7 >> 4) * 4;        // k group of 4
    const int jj   = (t7 & 15) * 2;        // j group of 2

    float2 acc00 = {0.f, 0.f}, acc01 = {0.f, 0.f};
    float2 acc10 = {0.f, 0.f}, acc11 = {0.f, 0.f};
    // acc{r}{p}: j = jj+r, k pair = {kk+2p, kk+2p+1}
    {
        const int dbeg = half * 64;
        #pragma unroll 8
        for (int d = dbeg; d < dbeg + 64; d++) {
            float4 x4 = *(const float4*)&sDt[d][kk];   // 16B aligned (TPAD=36)
            float2 y2 = *(const float2*)&sQt[d][jj];
            float2 xp0 = make_float2(x4.x, x4.y);
            float2 xp1 = make_float2(x4.z, x4.w);
            float2 yb0 = bcast2(y2.x);
            float2 yb1 = bcast2(y2.y);
            fma2(acc00, xp0, yb0);
            fma2(acc10, xp1, yb0);
            fma2(acc01, xp0, yb1);
            fma2(acc11, xp1, yb1);
        }
    }
    if (half == 1) {
        sL[kk + 0][jj]     = acc00.x; sL[kk + 1][jj]     = acc00.y;
        sL[kk + 2][jj]     = acc10.x; sL[kk + 3][jj]     = acc10.y;
        sL[kk + 0][jj + 1] = acc01.x; sL[kk + 1][jj + 1] = acc01.y;
        sL[kk + 2][jj + 1] = acc11.x; sL[kk + 3][jj + 1] = acc11.y;
    }
    __syncthreads();
    if (half == 0) {
        sL[kk + 0][jj]     += acc00.x; sL[kk + 1][jj]     += acc00.y;
        sL[kk + 2][jj]     += acc10.x; sL[kk + 3][jj]     += acc10.y;
        sL[kk + 0][jj + 1] += acc01.x; sL[kk + 1][jj + 1] += acc01.y;
        sL[kk + 2][jj + 1] += acc11.x; sL[kk + 3][jj + 1] += acc11.y;
    }
    __syncthreads();

    // ---- softmax stats: warp0 = per-column (AS), warp1 = per-row (AC) ----
    if (tid < 32) {
        const int j = tid;
        float mc = -1e30f;
        #pragma unroll
        for (int k = 0; k < KN; k++) mc = fmaxf(mc, sL[k][j]);
        float cs = 0.f;
        #pragma unroll
        for (int k = 0; k < KN; k++) cs += __expf(sL[k][j] - mc);
        sMc[j]   = mc;
        sCinv[j] = 1.0f / (32.0f * cs);
    } else if (tid < 64) {
        const int k = tid - 32;
        float mr = -1e30f;
        #pragma unroll
        for (int j = 0; j < KN; j++) mr = fmaxf(mr, sL[k][j]);
        float rs = 0.f;
        #pragma unroll
        for (int j = 0; j < KN; j++) rs += __expf(sL[k][j] - mr);
        sMr[k] = mr;
        sRs[k] = rs;
    }
    __syncthreads();

    // ---- w[j] = sum_k exp(L[j,k]-Mc[k]) / (32 c_k);  p = w / r ----
    if (tid < 32) {
        const int j = tid;
        float wj = 0.f;
        #pragma unroll
        for (int k = 0; k < KN; k++)
            wj += __expf(sL[j][k] - sMc[k]) * sCinv[k];
        sw[j]  = wj;
        sp_[j] = wj / sRs[j];
    }
    __syncthreads();

    // ---- v[j] = sum_k p[k] * exp(L[k,j]-Mr[k]) ----
    if (tid < 32) {
        const int j = tid;
        float vj = 0.f;
        #pragma unroll
        for (int k = 0; k < KN; k++)
            vj += sp_[k] * __expf(sL[k][j] - sMr[k]);
        sv[j] = vj;
    }
    __syncthreads();

    // ---- m = [mean_k Qm | w^T Dm | v^T Qm] ; j-rotated to kill 4-way conflicts ----
    if (tid < DF) {
        const int d   = tid;
        const int rot = ((d >> 3) & 3) << 3;   // 0,8,16,24 across conflicting lane groups
        float m1 = 0.f, m2 = 0.f, m3 = 0.f;
        #pragma unroll
        for (int it = 0; it < 16; it++) {
            const int j = (2 * it + rot) & 31;
            float2 q2 = *(const float2*)&sQt[d][j];
            float2 d2 = *(const float2*)&sDt[d][j];
            float2 w2 = *(const float2*)&sw[j];
            float2 v2 = *(const float2*)&sv[j];
            m1 += q2.x + q2.y;
            m2 += w2.x * d2.x + w2.y * d2.y;
            m3 += v2.x * q2.x + v2.y * q2.y;
        }
        sm[d]          = m1 * (1.0f / 32.0f);
        sm[DF + d]     = m2;
        sm[2 * DF + d] = m3;
    }
    __syncthreads();

    // ---- AvgPool1d(3,3) + residual ----
    if (tid < DF) {
        const int g = tid;
        float h = (sm[3 * g] + sm[3 * g + 1] + sm[3 * g + 2]) * (1.0f / 3.0f);
        out[(size_t)n * DF + g] = feat[(size_t)n * DF + g] + h;
    }
}

extern "C" void kernel_launch(void* const* d_in, const int* in_sizes, int n_in,
                              void* d_out, int out_size)
{
    const float* feat = (const float*)d_in[0];
    const int*   sim  = (const int*)d_in[1];
    const int*   cor  = (const int*)d_in[2];
    float*       out  = (float*)d_out;

    const int n_nodes = in_sizes[1] / KN;   // 20000
    coatt_kernel<<<n_nodes, 256>>>(feat, sim, cor, out);
}

// round 5
// speedup vs baseline: 1.4386x; 1.4386x over previous
#include <cuda_runtime.h>
#include <cstdint>

#define KN 32
#define DF 128
#define RP 132   // sDQ row pad (floats): 132 % 32 = 4 -> conflict-free frag/m-phase/gather maps
#define LP 34    // sL row pad

#define SDQ_FLOATS (2 * 64 * RP)        // 16896
#define SLB_FLOATS (2 * 4 * KN * LP)    // 8704
#define SMEM_BYTES ((SDQ_FLOATS + SLB_FLOATS + 7 * 64 + 2 * 384) * 4 + 2 * 64 * 4)

__device__ __forceinline__ unsigned f2tf(float x) {
    unsigned r; asm("cvt.rna.tf32.f32 %0, %1;" : "=r"(r) : "f"(x)); return r;
}
__device__ __forceinline__ void mma8(float* c, const unsigned* a, const unsigned* b) {
    asm volatile("mma.sync.aligned.m16n8k8.row.col.f32.tf32.tf32.f32 "
        "{%0,%1,%2,%3}, {%4,%5,%6,%7}, {%8,%9}, {%0,%1,%2,%3};"
        : "+f"(c[0]), "+f"(c[1]), "+f"(c[2]), "+f"(c[3])
        : "r"(a[0]), "r"(a[1]), "r"(a[2]), "r"(a[3]), "r"(b[0]), "r"(b[1]));
}

__global__ void __launch_bounds__(256, 2)
coatt_mma(const float* __restrict__ feat,
          const int* __restrict__ sim_idx,
          const int* __restrict__ cor_idx,
          float* __restrict__ out)
{
    extern __shared__ float sh[];
    float* sDQ  = sh;                        // [2][64][RP] rows 0-31 = Dm, 32-63 = Qm
    float* sLb  = sDQ + SDQ_FLOATS;          // [2][4][KN][LP] per-warp partials; buf0 = final L
    float* sMc  = sLb + SLB_FLOATS;          // [2][32] each below
    float* sCinv= sMc  + 64;
    float* sMr  = sCinv+ 64;
    float* sRs  = sMr  + 64;
    float* sw_  = sRs  + 64;
    float* sv_  = sw_  + 64;
    float* sp_  = sv_  + 64;
    int*   sIdx = (int*)(sp_ + 64);          // [2][64]
    float* sm_  = (float*)(sIdx + 128);      // [2][384]

    const int tid   = threadIdx.x;
    const int warp  = tid >> 5;
    const int lane  = tid & 31;
    const int nodeL = warp >> 2;             // 0/1: node within CTA
    const int q     = warp & 3;              // k-slice / role within node
    const int t128  = tid & 127;
    const size_t node = 2ull * blockIdx.x + nodeL;

    float* DQ  = sDQ + nodeL * 64 * RP;
    int*   idx = sIdx + nodeL * 64;

    // ---- neighbor indices: rows 0-31 sim (Dm), 32-63 cor (Qm) ----
    if (t128 < 64) {
        int r = t128;
        idx[r] = (r < KN) ? sim_idx[node * KN + r] : cor_idx[node * KN + (r - KN)];
    }
    __syncthreads();

    // ---- gather: warp q loads rows [16q, 16q+16); 4 rows/LDG (4 lines/instr) ----
    {
        const int jg = lane >> 3;            // 0..3 row-in-group
        const int c8 = lane & 7;             // float4 column 0..7
        int rws[4];
        #pragma unroll
        for (int it = 0; it < 4; it++) rws[it] = idx[16 * q + 4 * it + jg];
        #pragma unroll
        for (int it = 0; it < 4; it++) {
            const int r = 16 * q + 4 * it + jg;
            const float4* src = (const float4*)(feat + (size_t)rws[it] * DF);
            float* dst = DQ + r * RP;
            #pragma unroll
            for (int dc = 0; dc < 4; dc++) {
                float4 v = __ldg(src + dc * 8 + c8);
                *(float4*)(dst + 4 * (dc * 8 + c8)) = v;   // STS.128, 4-phase floor
            }
        }
    }
    __syncthreads();

    // ---- L partial via 3xTF32 mma: warp q does d in [32q, 32q+32) ----
    {
        float C[2][4][4];
        #pragma unroll
        for (int mi = 0; mi < 2; mi++)
            #pragma unroll
            for (int ni = 0; ni < 4; ni++)
                #pragma unroll
                for (int e = 0; e < 4; e++) C[mi][ni][e] = 0.f;

        const int r8 = lane >> 2, c4 = lane & 3;
        #pragma unroll
        for (int kt = 0; kt < 4; kt++) {
            const int d0 = 32 * q + 8 * kt;
            unsigned ah[2][4], al[2][4];
            #pragma unroll
            for (int mi = 0; mi < 2; mi++) {
                const float* base = DQ + (16 * mi + r8) * RP + d0 + c4;
                float a0 = base[0];
                float a1 = base[8 * RP];
                float a2 = base[4];
                float a3 = base[8 * RP + 4];
                ah[mi][0] = f2tf(a0); al[mi][0] = f2tf(a0 - __uint_as_float(ah[mi][0]));
                ah[mi][1] = f2tf(a1); al[mi][1] = f2tf(a1 - __uint_as_float(ah[mi][1]));
                ah[mi][2] = f2tf(a2); al[mi][2] = f2tf(a2 - __uint_as_float(ah[mi][2]));
                ah[mi][3] = f2tf(a3); al[mi][3] = f2tf(a3 - __uint_as_float(ah[mi][3]));
            }
            unsigned bh[4][2], bl[4][2];
            #pragma unroll
            for (int ni = 0; ni < 4; ni++) {
                const float* base = DQ + (32 + 8 * ni + r8) * RP + d0 + c4;
                float b0 = base[0];
                float b1 = base[4];
                bh[ni][0] = f2tf(b0); bl[ni][0] = f2tf(b0 - __uint_as_float(bh[ni][0]));
                bh[ni][1] = f2tf(b1); bl[ni][1] = f2tf(b1 - __uint_as_float(bh[ni][1]));
            }
            #pragma unroll
            for (int mi = 0; mi < 2; mi++)
                #pragma unroll
                for (int ni = 0; ni < 4; ni++) {
                    mma8(C[mi][ni], al[mi], bh[ni]);
                    mma8(C[mi][ni], ah[mi], bl[ni]);
                    mma8(C[mi][ni], ah[mi], bh[ni]);
                }
        }

        // store partial: sLb[nodeL][q]
        float* Lq = sLb + (nodeL * 4 + q) * KN * LP;
        const int cq = lane & 3;
        #pragma unroll
        for (int mi = 0; mi < 2; mi++)
            #pragma unroll
            for (int ni = 0; ni < 4; ni++) {
                const int row = 16 * mi + r8;
                const int col = 8 * ni + 2 * cq;
                *(float2*)(Lq + row * LP + col)       = make_float2(C[mi][ni][0], C[mi][ni][1]);
                *(float2*)(Lq + (row + 8) * LP + col) = make_float2(C[mi][ni][2], C[mi][ni][3]);
            }
    }
    __syncthreads();

    // ---- reduce 4 partials into buf0 ----
    {
        float* L0 = sLb + (nodeL * 4) * KN * LP;
        #pragma unroll
        for (int e = t128; e < KN * KN; e += 128) {
            const int o = (e >> 5) * LP + (e & 31);
            L0[o] = (L0[o] + L0[KN * LP + o]) + (L0[2 * KN * LP + o] + L0[3 * KN * LP + o]);
        }
    }
    __syncthreads();

    float* L0 = sLb + (nodeL * 4) * KN * LP;
    float* Mc = sMc + nodeL * 32;  float* Ci = sCinv + nodeL * 32;
    float* Mr = sMr + nodeL * 32;  float* Rs = sRs   + nodeL * 32;
    float* Wv = sw_ + nodeL * 32;  float* Vv = sv_   + nodeL * 32;
    float* Pv = sp_ + nodeL * 32;

    // ---- stage A: warp0 = col stats + w; warp1 = row stats ----
    if (q == 0) {
        const int j = lane;
        float mc = -1e30f;
        #pragma unroll
        for (int k = 0; k < KN; k++) mc = fmaxf(mc, L0[k * LP + j]);
        float cs = 0.f;
        #pragma unroll
        for (int k = 0; k < KN; k++) cs += __expf(L0[k * LP + j] - mc);
        Mc[j] = mc;
        Ci[j] = 1.0f / (32.0f * cs);
        __syncwarp();
        float wj = 0.f;
        #pragma unroll
        for (int k = 0; k < KN; k++)
            wj += __expf(L0[j * LP + k] - Mc[k]) * Ci[k];
        Wv[j] = wj;
    } else if (q == 1) {
        const int k = lane;
        float mr = -1e30f;
        #pragma unroll
        for (int j = 0; j < KN; j++) mr = fmaxf(mr, L0[k * LP + j]);
        float rs = 0.f;
        #pragma unroll
        for (int j = 0; j < KN; j++) rs += __expf(L0[k * LP + j] - mr);
        Mr[k] = mr;
        Rs[k] = rs;
    }
    __syncthreads();

    // ---- stage B: p = w/r ; v = AC^T p ----
    if (q == 0) {
        const int j = lane;
        Pv[j] = Wv[j] / Rs[j];
        __syncwarp();
        float vj = 0.f;
        #pragma unroll
        for (int k = 0; k < KN; k++)
            vj += Pv[k] * __expf(L0[k * LP + j] - Mr[k]);
        Vv[j] = vj;
    }
    __syncthreads();

    // ---- m = [mean_k Qm | w^T Dm | v^T Qm]  (bank = 4j + d, lanes d distinct) ----
    {
        const int d = t128;
        float m1 = 0.f, m2 = 0.f, m3 = 0.f;
        #pragma unroll
        for (int j = 0; j < KN; j++) {
            float dd = DQ[j * RP + d];
            float qq = DQ[(32 + j) * RP + d];
            m1 += qq;
            m2 += Wv[j] * dd;
            m3 += Vv[j] * qq;
        }
        float* sm = sm_ + nodeL * 384;
        sm[d]       = m1 * (1.0f / 32.0f);
        sm[128 + d] = m2;
        sm[256 + d] = m3;
    }
    __syncthreads();

    // ---- AvgPool1d(3,3) + residual ----
    {
        const int g = t128;
        const float* sm = sm_ + nodeL * 384;
        float h = (sm[3 * g] + sm[3 * g + 1] + sm[3 * g + 2]) * (1.0f / 3.0f);
        out[node * DF + g] = feat[node * DF + g] + h;
    }
}

extern "C" void kernel_launch(void* const* d_in, const int* in_sizes, int n_in,
                              void* d_out, int out_size)
{
    const float* feat = (const float*)d_in[0];
    const int*   sim  = (const int*)d_in[1];
    const int*   cor  = (const int*)d_in[2];
    float*       out  = (float*)d_out;

    const int n_nodes = in_sizes[1] / KN;    // 20000
    cudaFuncSetAttribute(coatt_mma, cudaFuncAttributeMaxDynamicSharedMemorySize, SMEM_BYTES);
    coatt_mma<<<n_nodes / 2, 256, SMEM_BYTES>>>(feat, sim, cor, out);
}

// round 6
// speedup vs baseline: 2.2995x; 1.5984x over previous
#include <cuda_runtime.h>
#include <cstdint>

#define KN 32
#define DF 128
#define RP 132   // DQ row pad (floats): 132 mod 32 = 4 -> conflict-free frag/m-phase maps, 16B rows
#define LP 36    // L row pad: STS.64 C-store dual-bank conflicts reduced to 2-way

// smem (floats): DQ [64][RP] = 8448 | Lb [2][32][LP] = 2304  (total 10752 fl = 42 KB)
// aliases: idx (64 int) on Lb slot0 (gather-time only); stats+sm on Lb slot1 (post-merge)
#define SMEM_FLOATS (64 * RP + 2 * KN * LP)
#define SMEM_BYTES  (SMEM_FLOATS * 4)

__device__ __forceinline__ unsigned f2tf(float x) {
    unsigned r; asm("cvt.rna.tf32.f32 %0, %1;" : "=r"(r) : "f"(x)); return r;
}
__device__ __forceinline__ void mma8(float* c, const unsigned* a, const unsigned* b) {
    asm volatile("mma.sync.aligned.m16n8k8.row.col.f32.tf32.tf32.f32 "
        "{%0,%1,%2,%3}, {%4,%5,%6,%7}, {%8,%9}, {%0,%1,%2,%3};"
        : "+f"(c[0]), "+f"(c[1]), "+f"(c[2]), "+f"(c[3])
        : "r"(a[0]), "r"(a[1]), "r"(a[2]), "r"(a[3]), "r"(b[0]), "r"(b[1]));
}
__device__ __forceinline__ void cpa16(uint32_t dst, const float* src) {
    asm volatile("cp.async.cg.shared.global [%0], [%1], 16;" :: "r"(dst), "l"(src));
}

__global__ void __launch_bounds__(128, 5)
coatt_mma(const float* __restrict__ feat,
          const int* __restrict__ sim_idx,
          const int* __restrict__ cor_idx,
          float* __restrict__ out)
{
    extern __shared__ float sh[];
    float* DQ  = sh;                       // [64][RP] rows 0-31 Dm, 32-63 Qm
    float* Lb0 = sh + 64 * RP;             // [32][LP]
    float* Lb1 = Lb0 + KN * LP;            // [32][LP]
    int*   idx = (int*)Lb0;                // alias (gather phase only)
    float* Mc  = Lb1;                      // aliases (post-merge)
    float* Ci  = Lb1 + 32;
    float* Mr  = Lb1 + 64;
    float* Rs  = Lb1 + 96;
    float* Wv  = Lb1 + 128;
    float* Vv  = Lb1 + 160;
    float* Pv  = Lb1 + 192;
    float* sm  = Lb1 + 224;                // [384]

    const int tid  = threadIdx.x;
    const int q    = tid >> 5;             // warp 0..3
    const int lane = tid & 31;
    const size_t node = blockIdx.x;

    // ---- neighbor indices: 0-31 sim (Dm rows), 32-63 cor (Qm rows) ----
    if (tid < 64)
        idx[tid] = (tid < KN) ? sim_idx[node * KN + tid]
                              : cor_idx[node * KN + (tid - KN)];
    __syncthreads();

    // ---- gather via cp.async: warp q owns rows [16q,16q+16) ----
    {
        const int jg = lane >> 3;          // 0..3
        const int c8 = lane & 7;           // 0..7
        #pragma unroll
        for (int it = 0; it < 4; it++) {
            const int r = 16 * q + 4 * it + jg;
            const float* src = feat + (size_t)idx[r] * DF;
            uint32_t dst = (uint32_t)__cvta_generic_to_shared(DQ + r * RP);
            #pragma unroll
            for (int dc = 0; dc < 4; dc++) {
                const int c4 = dc * 8 + c8;          // float4 index 0..31
                cpa16(dst + 16 * c4, src + 4 * c4);
            }
        }
        asm volatile("cp.async.commit_group;");
        asm volatile("cp.async.wait_group 0;");
    }
    __syncthreads();

    // ---- L partial via 3xTF32 mma: warp q covers d in [32q, 32q+32) ----
    float C[2][4][4];
    #pragma unroll
    for (int mi = 0; mi < 2; mi++)
        #pragma unroll
        for (int ni = 0; ni < 4; ni++)
            #pragma unroll
            for (int e = 0; e < 4; e++) C[mi][ni][e] = 0.f;

    const int r8 = lane >> 2, c4 = lane & 3;
    #pragma unroll
    for (int kt = 0; kt < 4; kt++) {
        const int d0 = 32 * q + 8 * kt;
        unsigned ah[2][4], al[2][4];
        #pragma unroll
        for (int mi = 0; mi < 2; mi++) {
            const float* base = DQ + (16 * mi + r8) * RP + d0 + c4;
            float a0 = base[0];
            float a1 = base[8 * RP];
            float a2 = base[4];
            float a3 = base[8 * RP + 4];
            ah[mi][0] = f2tf(a0); al[mi][0] = f2tf(a0 - __uint_as_float(ah[mi][0]));
            ah[mi][1] = f2tf(a1); al[mi][1] = f2tf(a1 - __uint_as_float(ah[mi][1]));
            ah[mi][2] = f2tf(a2); al[mi][2] = f2tf(a2 - __uint_as_float(ah[mi][2]));
            ah[mi][3] = f2tf(a3); al[mi][3] = f2tf(a3 - __uint_as_float(ah[mi][3]));
        }
        unsigned bh[4][2], bl[4][2];
        #pragma unroll
        for (int ni = 0; ni < 4; ni++) {
            const float* base = DQ + (32 + 8 * ni + r8) * RP + d0 + c4;
            float b0 = base[0];
            float b1 = base[4];
            bh[ni][0] = f2tf(b0); bl[ni][0] = f2tf(b0 - __uint_as_float(bh[ni][0]));
            bh[ni][1] = f2tf(b1); bl[ni][1] = f2tf(b1 - __uint_as_float(bh[ni][1]));
        }
        #pragma unroll
        for (int mi = 0; mi < 2; mi++)
            #pragma unroll
            for (int ni = 0; ni < 4; ni++) {
                mma8(C[mi][ni], al[mi], bh[ni]);
                mma8(C[mi][ni], ah[mi], bl[ni]);
                mma8(C[mi][ni], ah[mi], bh[ni]);
            }
    }

    // ---- partial reduce: q0/q1 store to slots, q2/q3 add, then 128-thr merge ----
    {
        float* Lq = (q & 1) ? Lb1 : Lb0;
        const int cq = lane & 3;
        if (q < 2) {
            #pragma unroll
            for (int mi = 0; mi < 2; mi++)
                #pragma unroll
                for (int ni = 0; ni < 4; ni++) {
                    const int row = 16 * mi + r8;
                    const int col = 8 * ni + 2 * cq;
                    *(float2*)(Lq + row * LP + col)       = make_float2(C[mi][ni][0], C[mi][ni][1]);
                    *(float2*)(Lq + (row + 8) * LP + col) = make_float2(C[mi][ni][2], C[mi][ni][3]);
                }
        }
        __syncthreads();
        if (q >= 2) {
            #pragma unroll
            for (int mi = 0; mi < 2; mi++)
                #pragma unroll
                for (int ni = 0; ni < 4; ni++) {
                    const int row = 16 * mi + r8;
                    const int col = 8 * ni + 2 * cq;
                    float2 t0 = *(float2*)(Lq + row * LP + col);
                    float2 t1 = *(float2*)(Lq + (row + 8) * LP + col);
                    t0.x += C[mi][ni][0]; t0.y += C[mi][ni][1];
                    t1.x += C[mi][ni][2]; t1.y += C[mi][ni][3];
                    *(float2*)(Lq + row * LP + col)       = t0;
                    *(float2*)(Lq + (row + 8) * LP + col) = t1;
                }
        }
        __syncthreads();
        // merge slot1 into slot0 (conflict-free: lanes -> consecutive cols)
        #pragma unroll
        for (int e = tid; e < KN * KN; e += 128) {
            const int o = (e >> 5) * LP + (e & 31);
            Lb0[o] += Lb1[o];
        }
        __syncthreads();
    }

    // ---- stage A: warp0 = col stats + w ; warp1 = row stats ----
    if (q == 0) {
        const int j = lane;
        float mc = -1e30f;
        #pragma unroll
        for (int k = 0; k < KN; k++) mc = fmaxf(mc, Lb0[k * LP + j]);
        float cs = 0.f;
        #pragma unroll
        for (int k = 0; k < KN; k++) cs += __expf(Lb0[k * LP + j] - mc);
        Mc[j] = mc;
        Ci[j] = 1.0f / (32.0f * cs);
        __syncwarp();
        // w: row-direction, vectorized float4 reads
        float wj = 0.f;
        const float* rowj = Lb0 + j * LP;
        #pragma unroll
        for (int j4 = 0; j4 < 8; j4++) {
            float4 v = *(const float4*)(rowj + 4 * j4);
            const int k = 4 * j4;
            wj += __expf(v.x - Mc[k + 0]) * Ci[k + 0];
            wj += __expf(v.y - Mc[k + 1]) * Ci[k + 1];
            wj += __expf(v.z - Mc[k + 2]) * Ci[k + 2];
            wj += __expf(v.w - Mc[k + 3]) * Ci[k + 3];
        }
        Wv[j] = wj;
    } else if (q == 1) {
        const int k = lane;
        const float* rowk = Lb0 + k * LP;
        float mr = -1e30f;
        #pragma unroll
        for (int j4 = 0; j4 < 8; j4++) {
            float4 v = *(const float4*)(rowk + 4 * j4);
            mr = fmaxf(mr, fmaxf(fmaxf(v.x, v.y), fmaxf(v.z, v.w)));
        }
        float rs = 0.f;
        #pragma unroll
        for (int j4 = 0; j4 < 8; j4++) {
            float4 v = *(const float4*)(rowk + 4 * j4);
            rs += __expf(v.x - mr) + __expf(v.y - mr) + __expf(v.z - mr) + __expf(v.w - mr);
        }
        Mr[k] = mr;
        Rs[k] = rs;
    }
    __syncthreads();

    // ---- stage B: p = w/r ; v = AC^T p (column reads, conflict-free) ----
    if (q == 0) {
        const int j = lane;
        Pv[j] = Wv[j] / Rs[j];
        __syncwarp();
        float vj = 0.f;
        #pragma unroll
        for (int k = 0; k < KN; k++)
            vj += Pv[k] * __expf(Lb0[k * LP + j] - Mr[k]);
        Vv[j] = vj;
    }
    __syncthreads();

    // ---- m = [mean_k Qm | w^T Dm | v^T Qm] (bank 4j+d, lanes distinct) ----
    {
        const int d = tid;
        float m1 = 0.f, m2 = 0.f, m3 = 0.f;
        #pragma unroll
        for (int j = 0; j < KN; j++) {
            float dd = DQ[j * RP + d];
            float qq = DQ[(32 + j) * RP + d];
            m1 += qq;
            m2 += Wv[j] * dd;
            m3 += Vv[j] * qq;
        }
        sm[d]       = m1 * (1.0f / 32.0f);
        sm[128 + d] = m2;
        sm[256 + d] = m3;
    }
    __syncthreads();

    // ---- AvgPool1d(3,3) + residual ----
    {
        const int g = tid;
        float h = (sm[3 * g] + sm[3 * g + 1] + sm[3 * g + 2]) * (1.0f / 3.0f);
        out[node * DF + g] = feat[node * DF + g] + h;
    }
}

extern "C" void kernel_launch(void* const* d_in, const int* in_sizes, int n_in,
                              void* d_out, int out_size)
{
    const float* feat = (const float*)d_in[0];
    const int*   sim  = (const int*)d_in[1];
    const int*   cor  = (const int*)d_in[2];
    float*       out  = (float*)d_out;

    const int n_nodes = in_sizes[1] / KN;    // 20000
    cudaFuncSetAttribute(coatt_mma, cudaFuncAttributeMaxDynamicSharedMemorySize, SMEM_BYTES);
    coatt_mma<<<n_nodes, 128, SMEM_BYTES>>>(feat, sim, cor, out);
}

// round 8
// speedup vs baseline: 2.3580x; 1.0254x over previous
#include <cuda_runtime.h>
#include <cstdint>

#define KN 32
#define DF 128
#define RP 132   // DQ row pad: 132 mod 32 = 4 -> conflict-free frag/m-phase maps, 16B rows
#define LP 36    // L row pad: float2/float4 aligned, col reads conflict-free

// smem floats: DQ 64*RP=8448 | Lb 2*32*LP=2304 | stats 384  -> 44544 B, 5 CTAs/SM
#define SMEM_FLOATS (64 * RP + 2 * KN * LP + 384)
#define SMEM_BYTES  (SMEM_FLOATS * 4)

__device__ __forceinline__ unsigned f2tf(float x) {
    unsigned r; asm("cvt.rna.tf32.f32 %0, %1;" : "=r"(r) : "f"(x)); return r;
}
__device__ __forceinline__ void mma8(float* c, const unsigned* a, const unsigned* b) {
    asm volatile("mma.sync.aligned.m16n8k8.row.col.f32.tf32.tf32.f32 "
        "{%0,%1,%2,%3}, {%4,%5,%6,%7}, {%8,%9}, {%0,%1,%2,%3};"
        : "+f"(c[0]), "+f"(c[1]), "+f"(c[2]), "+f"(c[3])
        : "r"(a[0]), "r"(a[1]), "r"(a[2]), "r"(a[3]), "r"(b[0]), "r"(b[1]));
}
__device__ __forceinline__ void cpa16(uint32_t dst, const float* src) {
    asm volatile("cp.async.cg.shared.global [%0], [%1], 16;" :: "r"(dst), "l"(src));
}

__global__ void __launch_bounds__(128, 5)
coatt_mma(const float* __restrict__ feat,
          const int* __restrict__ sim_idx,
          const int* __restrict__ cor_idx,
          float* __restrict__ out)
{
    extern __shared__ float sh[];
    float* DQ    = sh;                     // [64][RP] rows 0-31 Dm, 32-63 Qm
    float* Lb0   = sh + 64 * RP;           // [32][LP] partial L (warps 0,2)
    float* Lb1   = Lb0 + KN * LP;          // [32][LP] partial L (warps 1,3)
    float* stats = Lb1 + KN * LP;
    float* Mc = stats;                     // col max   -> later Wv
    float* Ci = stats + 32;                // 1/(32*colsum) -> later Vv
    float* Mr = stats + 64;                // row max
    float* Rs = stats + 96;                // row sum
    float* Wp = stats + 128;               // [4][32] w partials
    float* Vp = stats + 256;               // [4][32] v partials
    int*   idx = (int*)Lb0;                // alias: used only before L written
    float* sm  = Lb0;                      // alias: written after L dead

    const int tid  = threadIdx.x;
    const int q    = tid >> 5;
    const int lane = tid & 31;
    const size_t node = blockIdx.x;

    // ---- early residual prefetch (hides tail LDG) ----
    const float res = __ldg(feat + node * DF + tid);

    // ---- neighbor indices: 0-31 sim (Dm rows), 32-63 cor (Qm rows) ----
    if (tid < 64)
        idx[tid] = (tid < KN) ? sim_idx[node * KN + tid]
                              : cor_idx[node * KN + (tid - KN)];
    __syncthreads();

    // ---- gather via cp.async: warp q owns rows [16q,16q+16) ----
    {
        const int jg = lane >> 3;
        const int c8 = lane & 7;
        #pragma unroll
        for (int it = 0; it < 4; it++) {
            const int r = 16 * q + 4 * it + jg;
            const float* src = feat + (size_t)idx[r] * DF;
            uint32_t dst = (uint32_t)__cvta_generic_to_shared(DQ + r * RP);
            #pragma unroll
            for (int dc = 0; dc < 4; dc++) {
                const int c4 = dc * 8 + c8;
                cpa16(dst + 16 * c4, src + 4 * c4);
            }
        }
        asm volatile("cp.async.commit_group;");
        asm volatile("cp.async.wait_group 0;");
    }
    __syncthreads();

    // ---- L partial via 3xTF32 mma: warp q covers d in [32q, 32q+32) ----
    float C[2][4][4];
    #pragma unroll
    for (int mi = 0; mi < 2; mi++)
        #pragma unroll
        for (int ni = 0; ni < 4; ni++)
            #pragma unroll
            for (int e = 0; e < 4; e++) C[mi][ni][e] = 0.f;

    const int r8 = lane >> 2, c4 = lane & 3;
    #pragma unroll
    for (int kt = 0; kt < 4; kt++) {
        const int d0 = 32 * q + 8 * kt;
        unsigned ah[2][4], al[2][4];
        #pragma unroll
        for (int mi = 0; mi < 2; mi++) {
            const float* base = DQ + (16 * mi + r8) * RP + d0 + c4;
            float a0 = base[0];
            float a1 = base[8 * RP];
            float a2 = base[4];
            float a3 = base[8 * RP + 4];
            ah[mi][0] = f2tf(a0); al[mi][0] = f2tf(a0 - __uint_as_float(ah[mi][0]));
            ah[mi][1] = f2tf(a1); al[mi][1] = f2tf(a1 - __uint_as_float(ah[mi][1]));
            ah[mi][2] = f2tf(a2); al[mi][2] = f2tf(a2 - __uint_as_float(ah[mi][2]));
            ah[mi][3] = f2tf(a3); al[mi][3] = f2tf(a3 - __uint_as_float(ah[mi][3]));
        }
        unsigned bh[4][2], bl[4][2];
        #pragma unroll
        for (int ni = 0; ni < 4; ni++) {
            const float* base = DQ + (32 + 8 * ni + r8) * RP + d0 + c4;
            float b0 = base[0];
            float b1 = base[4];
            bh[ni][0] = f2tf(b0); bl[ni][0] = f2tf(b0 - __uint_as_float(bh[ni][0]));
            bh[ni][1] = f2tf(b1); bl[ni][1] = f2tf(b1 - __uint_as_float(bh[ni][1]));
        }
        #pragma unroll
        for (int mi = 0; mi < 2; mi++)
            #pragma unroll
            for (int ni = 0; ni < 4; ni++) {
                mma8(C[mi][ni], al[mi], bh[ni]);
                mma8(C[mi][ni], ah[mi], bl[ni]);
                mma8(C[mi][ni], ah[mi], bh[ni]);
            }
    }

    // ---- partial reduce to two slots: q0/q1 store, q2/q3 add ----
    {
        float* Lq = (q & 1) ? Lb1 : Lb0;
        const int cq = lane & 3;
        if (q < 2) {
            #pragma unroll
            for (int mi = 0; mi < 2; mi++)
                #pragma unroll
                for (int ni = 0; ni < 4; ni++) {
                    const int row = 16 * mi + r8;
                    const int col = 8 * ni + 2 * cq;
                    *(float2*)(Lq + row * LP + col)       = make_float2(C[mi][ni][0], C[mi][ni][1]);
                    *(float2*)(Lq + (row + 8) * LP + col) = make_float2(C[mi][ni][2], C[mi][ni][3]);
                }
        }
        __syncthreads();
        if (q >= 2) {
            #pragma unroll
            for (int mi = 0; mi < 2; mi++)
                #pragma unroll
                for (int ni = 0; ni < 4; ni++) {
                    const int row = 16 * mi + r8;
                    const int col = 8 * ni + 2 * cq;
                    float2 t0 = *(float2*)(Lq + row * LP + col);
                    float2 t1 = *(float2*)(Lq + (row + 8) * LP + col);
                    t0.x += C[mi][ni][0]; t0.y += C[mi][ni][1];
                    t1.x += C[mi][ni][2]; t1.y += C[mi][ni][3];
                    *(float2*)(Lq + row * LP + col)       = t0;
                    *(float2*)(Lq + (row + 8) * LP + col) = t1;
                }
        }
        __syncthreads();
    }
    // L[r][c] = Lb0[r][c] + Lb1[r][c] from here on (no merge pass)

    // ---- stats: warp0 col max/sum (scalar, conflict-free), warp1 row (rotated float4) ----
    if (q == 0) {
        const int j = lane;
        float mc = -1e30f;
        #pragma unroll
        for (int k = 0; k < KN; k++)
            mc = fmaxf(mc, Lb0[k * LP + j] + Lb1[k * LP + j]);
        float cs = 0.f;
        #pragma unroll
        for (int k = 0; k < KN; k++)
            cs += __expf(Lb0[k * LP + j] + Lb1[k * LP + j] - mc);
        Mc[j] = mc;
        Ci[j] = 1.0f / (32.0f * cs);
    } else if (q == 1) {
        const int k = lane;
        const float* ra = Lb0 + k * LP;
        const float* rb = Lb1 + k * LP;
        float mr = -1e30f;
        #pragma unroll
        for (int i = 0; i < 8; i++) {
            const int cc = 4 * ((i + (k >> 3)) & 7);     // rotation: conflict-free
            float4 va = *(const float4*)(ra + cc);
            float4 vb = *(const float4*)(rb + cc);
            mr = fmaxf(mr, fmaxf(fmaxf(va.x + vb.x, va.y + vb.y),
                                 fmaxf(va.z + vb.z, va.w + vb.w)));
        }
        float rs = 0.f;
        #pragma unroll
        for (int i = 0; i < 8; i++) {
            const int cc = 4 * ((i + (k >> 3)) & 7);
            float4 va = *(const float4*)(ra + cc);
            float4 vb = *(const float4*)(rb + cc);
            rs += __expf(va.x + vb.x - mr) + __expf(va.y + vb.y - mr)
                + __expf(va.z + vb.z - mr) + __expf(va.w + vb.w - mr);
        }
        Mr[k] = mr;
        Rs[k] = rs;
    }
    __syncthreads();

    // ---- w partials: all 4 warps, rotated k-chunk (conflict-free rows) ----
    // w[j] = sum_k exp(L[j,k]-Mc[k]) * Ci[k]; warp q handles chunk (q + j/8) & 3
    {
        const int j  = lane;
        const int k0 = 8 * ((q + (j >> 3)) & 3);
        const float* pa = Lb0 + j * LP + k0;
        const float* pb = Lb1 + j * LP + k0;
        float4 a0 = *(const float4*)pa,       b0 = *(const float4*)pb;
        float4 a1 = *(const float4*)(pa + 4), b1 = *(const float4*)(pb + 4);
        float wj;
        wj  = __expf(a0.x + b0.x - Mc[k0 + 0]) * Ci[k0 + 0];
        wj += __expf(a0.y + b0.y - Mc[k0 + 1]) * Ci[k0 + 1];
        wj += __expf(a0.z + b0.z - Mc[k0 + 2]) * Ci[k0 + 2];
        wj += __expf(a0.w + b0.w - Mc[k0 + 3]) * Ci[k0 + 3];
        wj += __expf(a1.x + b1.x - Mc[k0 + 4]) * Ci[k0 + 4];
        wj += __expf(a1.y + b1.y - Mc[k0 + 5]) * Ci[k0 + 5];
        wj += __expf(a1.z + b1.z - Mc[k0 + 6]) * Ci[k0 + 6];
        wj += __expf(a1.w + b1.w - Mc[k0 + 7]) * Ci[k0 + 7];
        Wp[q * 32 + j] = wj;
    }
    __syncthreads();

    // ---- v partials: all 4 warps, k-range [8q,8q+8), column reads (conflict-free) ----
    // v[j] = sum_k (w[k]/Rs[k]) * exp(L[k,j]-Mr[k])
    {
        const int j = lane;
        float vj = 0.f;
        #pragma unroll
        for (int i = 0; i < 8; i++) {
            const int k = 8 * q + i;
            float wk = ((Wp[k] + Wp[32 + k]) + (Wp[64 + k] + Wp[96 + k]));  // uniform
            float pk = __fdividef(wk, Rs[k]);
            vj += pk * __expf(Lb0[k * LP + j] + Lb1[k * LP + j] - Mr[k]);
        }
        Vp[q * 32 + j] = vj;
    }
    __syncthreads();

    // ---- reduce Wv, Vv once (warp0) into Mc/Ci (dead) ----
    if (tid < 32) {
        const int j = tid;
        Mc[j] = (Wp[j] + Wp[32 + j]) + (Wp[64 + j] + Wp[96 + j]);   // Wv
        Ci[j] = (Vp[j] + Vp[32 + j]) + (Vp[64 + j] + Vp[96 + j]);   // Vv
    }
    __syncthreads();

    // ---- m = [mean_k Qm | w^T Dm | v^T Qm] (bank 4j+d, lanes distinct; Wv/Vv bcast) ----
    {
        const int d = tid;
        float m1 = 0.f, m2 = 0.f, m3 = 0.f;
        #pragma unroll
        for (int j = 0; j < KN; j++) {
            float dd = DQ[j * RP + d];
            float qq = DQ[(32 + j) * RP + d];
            m1 += qq;
            m2 += Mc[j] * dd;     // Wv
            m3 += Ci[j] * qq;     // Vv
        }
        sm[d]       = m1 * (1.0f / 32.0f);
        sm[128 + d] = m2;
        sm[256 + d] = m3;
    }
    __syncthreads();

    // ---- AvgPool1d(3,3) + residual (prefetched) ----
    {
        const int g = tid;
        float h = (sm[3 * g] + sm[3 * g + 1] + sm[3 * g + 2]) * (1.0f / 3.0f);
        out[node * DF + g] = res + h;
    }
}

extern "C" void kernel_launch(void* const* d_in, const int* in_sizes, int n_in,
                              void* d_out, int out_size)
{
    const float* feat = (const float*)d_in[0];
    const int*   sim  = (const int*)d_in[1];
    const int*   cor  = (const int*)d_in[2];
    float*       out  = (float*)d_out;

    const int n_nodes = in_sizes[1] / KN;    // 20000
    cudaFuncSetAttribute(coatt_mma, cudaFuncAttributeMaxDynamicSharedMemorySize, SMEM_BYTES);
    coatt_mma<<<n_nodes, 128, SMEM_BYTES>>>(feat, sim, cor, out);
}

// round 9
// speedup vs baseline: 2.4823x; 1.0527x over previous
#include <cuda_runtime.h>
#include <cstdint>

#define KN 32
#define DF 128
#define RP 132   // DQ row pad: 132 mod 32 = 4 -> conflict-free frag/m-phase maps, 16B rows
#define LP 36    // L row pad: float2/float4 aligned, col reads conflict-free

// smem floats: DQ 64*RP=8448 | Lb 2*32*LP=2304 | stats 384  -> 44544 B, 5 CTAs/SM
#define SMEM_FLOATS (64 * RP + 2 * KN * LP + 384)
#define SMEM_BYTES  (SMEM_FLOATS * 4)

// pack two f32 into bf16x2 (e0 -> low half, e1 -> high half)
__device__ __forceinline__ unsigned bfpack(float e0, float e1) {
    unsigned r; asm("cvt.rn.bf16x2.f32 %0, %1, %2;" : "=r"(r) : "f"(e1), "f"(e0)); return r;
}
// split f32 pair into (hi bf16x2, lo bf16x2)
__device__ __forceinline__ void bfsplit(float e0, float e1, unsigned& hi, unsigned& lo) {
    hi = bfpack(e0, e1);
    float h0 = __uint_as_float(hi << 16);
    float h1 = __uint_as_float(hi & 0xFFFF0000u);
    lo = bfpack(e0 - h0, e1 - h1);
}
__device__ __forceinline__ void mma16(float* c, const unsigned* a, const unsigned* b) {
    asm volatile("mma.sync.aligned.m16n8k16.row.col.f32.bf16.bf16.f32 "
        "{%0,%1,%2,%3}, {%4,%5,%6,%7}, {%8,%9}, {%0,%1,%2,%3};"
        : "+f"(c[0]), "+f"(c[1]), "+f"(c[2]), "+f"(c[3])
        : "r"(a[0]), "r"(a[1]), "r"(a[2]), "r"(a[3]), "r"(b[0]), "r"(b[1]));
}
__device__ __forceinline__ void cpa16(uint32_t dst, const float* src) {
    asm volatile("cp.async.cg.shared.global [%0], [%1], 16;" :: "r"(dst), "l"(src));
}

__global__ void __launch_bounds__(128, 5)
coatt_mma(const float* __restrict__ feat,
          const int* __restrict__ sim_idx,
          const int* __restrict__ cor_idx,
          float* __restrict__ out)
{
    extern __shared__ float sh[];
    float* DQ    = sh;                     // [64][RP] rows 0-31 Dm, 32-63 Qm
    float* Lb0   = sh + 64 * RP;           // [32][LP] partial L (warps 0,2)
    float* Lb1   = Lb0 + KN * LP;          // [32][LP] partial L (warps 1,3)
    float* stats = Lb1 + KN * LP;
    float* Mc = stats;                     // col max   -> later Wv
    float* Ci = stats + 32;                // 1/(32*colsum) -> later Vv
    float* Mr = stats + 64;                // row max
    float* Rs = stats + 96;                // row sum
    float* Wp = stats + 128;               // [4][32] w partials
    float* Vp = stats + 256;               // [4][32] v partials
    float* sm = Lb0;                       // alias: written after L dead

    const int tid  = threadIdx.x;
    const int q    = tid >> 5;
    const int lane = tid & 31;
    const size_t node = blockIdx.x;

    // ---- early residual prefetch (hides tail LDG) ----
    const float res = __ldg(feat + node * DF + tid);

    // ---- neighbor indices via LDG + shfl (no smem stage, no barrier) ----
    // warp q owns rows [16q,16q+16): rows 0-31 sim (Dm), 32-63 cor (Qm)
    int rowidx = 0;
    {
        const int gr = 16 * q + (lane & 15);
        if (lane < 16)
            rowidx = (gr < KN) ? __ldg(sim_idx + node * KN + gr)
                               : __ldg(cor_idx + node * KN + gr - KN);
    }

    // ---- gather via cp.async ----
    {
        const int jg = lane >> 3;          // 0..3
        const int c8 = lane & 7;           // 0..7
        #pragma unroll
        for (int it = 0; it < 4; it++) {
            const int rloc = 4 * it + jg;                    // 0..15 within warp
            const int ridx = __shfl_sync(0xffffffffu, rowidx, rloc);
            const int r    = 16 * q + rloc;
            const float* src = feat + (size_t)ridx * DF;
            uint32_t dst = (uint32_t)__cvta_generic_to_shared(DQ + r * RP);
            #pragma unroll
            for (int dc = 0; dc < 4; dc++) {
                const int c4 = dc * 8 + c8;
                cpa16(dst + 16 * c4, src + 4 * c4);
            }
        }
        asm volatile("cp.async.commit_group;");
        asm volatile("cp.async.wait_group 0;");
    }
    __syncthreads();

    // ---- L partial via split-bf16 3-term mma (k16): warp q covers d in [32q,32q+32) ----
    float C[2][4][4];
    #pragma unroll
    for (int mi = 0; mi < 2; mi++)
        #pragma unroll
        for (int ni = 0; ni < 4; ni++)
            #pragma unroll
            for (int e = 0; e < 4; e++) C[mi][ni][e] = 0.f;

    const int r8 = lane >> 2;              // 0..7
    const int c4 = lane & 3;               // 0..3
    #pragma unroll
    for (int kt = 0; kt < 2; kt++) {
        const int d0 = 32 * q + 16 * kt;
        // A fragments: rows 16mi + r8 (+8), k = d0 + 2c4 (+1) and +8
        unsigned ah[2][4], al[2][4];
        #pragma unroll
        for (int mi = 0; mi < 2; mi++) {
            const float* base = DQ + (16 * mi + r8) * RP + d0 + 2 * c4;
            float2 p0 = *(const float2*)(base);                //  (r,   klo)
            float2 p1 = *(const float2*)(base + 8 * RP);       //  (r+8, klo)
            float2 p2 = *(const float2*)(base + 8);            //  (r,   khi)
            float2 p3 = *(const float2*)(base + 8 * RP + 8);   //  (r+8, khi)
            bfsplit(p0.x, p0.y, ah[mi][0], al[mi][0]);
            bfsplit(p1.x, p1.y, ah[mi][1], al[mi][1]);
            bfsplit(p2.x, p2.y, ah[mi][2], al[mi][2]);
            bfsplit(p3.x, p3.y, ah[mi][3], al[mi][3]);
        }
        // B fragments: col n = 8ni + r8, k = d0 + 2c4 (+1) and +8
        unsigned bh[4][2], bl[4][2];
        #pragma unroll
        for (int ni = 0; ni < 4; ni++) {
            const float* base = DQ + (32 + 8 * ni + r8) * RP + d0 + 2 * c4;
            float2 p0 = *(const float2*)(base);
            float2 p1 = *(const float2*)(base + 8);
            bfsplit(p0.x, p0.y, bh[ni][0], bl[ni][0]);
            bfsplit(p1.x, p1.y, bh[ni][1], bl[ni][1]);
        }
        #pragma unroll
        for (int mi = 0; mi < 2; mi++)
            #pragma unroll
            for (int ni = 0; ni < 4; ni++) {
                mma16(C[mi][ni], al[mi], bh[ni]);
                mma16(C[mi][ni], ah[mi], bl[ni]);
                mma16(C[mi][ni], ah[mi], bh[ni]);
            }
    }

    // ---- partial reduce to two slots: q0/q1 store, q2/q3 add ----
    {
        float* Lq = (q & 1) ? Lb1 : Lb0;
        if (q < 2) {
            #pragma unroll
            for (int mi = 0; mi < 2; mi++)
                #pragma unroll
                for (int ni = 0; ni < 4; ni++) {
                    const int row = 16 * mi + r8;
                    const int col = 8 * ni + 2 * c4;
                    *(float2*)(Lq + row * LP + col)       = make_float2(C[mi][ni][0], C[mi][ni][1]);
                    *(float2*)(Lq + (row + 8) * LP + col) = make_float2(C[mi][ni][2], C[mi][ni][3]);
                }
        }
        __syncthreads();
        if (q >= 2) {
            #pragma unroll
            for (int mi = 0; mi < 2; mi++)
                #pragma unroll
                for (int ni = 0; ni < 4; ni++) {
                    const int row = 16 * mi + r8;
                    const int col = 8 * ni + 2 * c4;
                    float2 t0 = *(float2*)(Lq + row * LP + col);
                    float2 t1 = *(float2*)(Lq + (row + 8) * LP + col);
                    t0.x += C[mi][ni][0]; t0.y += C[mi][ni][1];
                    t1.x += C[mi][ni][2]; t1.y += C[mi][ni][3];
                    *(float2*)(Lq + row * LP + col)       = t0;
                    *(float2*)(Lq + (row + 8) * LP + col) = t1;
                }
        }
        __syncthreads();
    }
    // L[r][c] = Lb0[r][c] + Lb1[r][c] from here on (no merge pass)

    // ---- stats: warp0 col max/sum (scalar, conflict-free), warp1 row (rotated float4) ----
    if (q == 0) {
        const int j = lane;
        float mc = -1e30f;
        #pragma unroll
        for (int k = 0; k < KN; k++)
            mc = fmaxf(mc, Lb0[k * LP + j] + Lb1[k * LP + j]);
        float cs = 0.f;
        #pragma unroll
        for (int k = 0; k < KN; k++)
            cs += __expf(Lb0[k * LP + j] + Lb1[k * LP + j] - mc);
        Mc[j] = mc;
        Ci[j] = 1.0f / (32.0f * cs);
    } else if (q == 1) {
        const int k = lane;
        const float* ra = Lb0 + k * LP;
        const float* rb = Lb1 + k * LP;
        float mr = -1e30f;
        #pragma unroll
        for (int i = 0; i < 8; i++) {
            const int cc = 4 * ((i + (k >> 3)) & 7);     // rotation: conflict-free
            float4 va = *(const float4*)(ra + cc);
            float4 vb = *(const float4*)(rb + cc);
            mr = fmaxf(mr, fmaxf(fmaxf(va.x + vb.x, va.y + vb.y),
                                 fmaxf(va.z + vb.z, va.w + vb.w)));
        }
        float rs = 0.f;
        #pragma unroll
        for (int i = 0; i < 8; i++) {
            const int cc = 4 * ((i + (k >> 3)) & 7);
            float4 va = *(const float4*)(ra + cc);
            float4 vb = *(const float4*)(rb + cc);
            rs += __expf(va.x + vb.x - mr) + __expf(va.y + vb.y - mr)
                + __expf(va.z + vb.z - mr) + __expf(va.w + vb.w - mr);
        }
        Mr[k] = mr;
        Rs[k] = rs;
    }
    __syncthreads();

    // ---- w partials: all 4 warps, rotated k-chunk (conflict-free rows) ----
    // w[j] = sum_k exp(L[j,k]-Mc[k]) * Ci[k]; warp q handles chunk (q + j/8) & 3
    {
        const int j  = lane;
        const int k0 = 8 * ((q + (j >> 3)) & 3);
        const float* pa = Lb0 + j * LP + k0;
        const float* pb = Lb1 + j * LP + k0;
        float4 a0 = *(const float4*)pa,       b0 = *(const float4*)pb;
        float4 a1 = *(const float4*)(pa + 4), b1 = *(const float4*)(pb + 4);
        float wj;
        wj  = __expf(a0.x + b0.x - Mc[k0 + 0]) * Ci[k0 + 0];
        wj += __expf(a0.y + b0.y - Mc[k0 + 1]) * Ci[k0 + 1];
        wj += __expf(a0.z + b0.z - Mc[k0 + 2]) * Ci[k0 + 2];
        wj += __expf(a0.w + b0.w - Mc[k0 + 3]) * Ci[k0 + 3];
        wj += __expf(a1.x + b1.x - Mc[k0 + 4]) * Ci[k0 + 4];
        wj += __expf(a1.y + b1.y - Mc[k0 + 5]) * Ci[k0 + 5];
        wj += __expf(a1.z + b1.z - Mc[k0 + 6]) * Ci[k0 + 6];
        wj += __expf(a1.w + b1.w - Mc[k0 + 7]) * Ci[k0 + 7];
        Wp[q * 32 + j] = wj;
    }
    __syncthreads();

    // ---- v partials: all 4 warps, k-range [8q,8q+8), column reads (conflict-free) ----
    // v[j] = sum_k (w[k]/Rs[k]) * exp(L[k,j]-Mr[k])
    {
        const int j = lane;
        float vj = 0.f;
        #pragma unroll
        for (int i = 0; i < 8; i++) {
            const int k = 8 * q + i;
            float wk = ((Wp[k] + Wp[32 + k]) + (Wp[64 + k] + Wp[96 + k]));  // uniform
            float pk = __fdividef(wk, Rs[k]);
            vj += pk * __expf(Lb0[k * LP + j] + Lb1[k * LP + j] - Mr[k]);
        }
        Vp[q * 32 + j] = vj;
    }
    __syncthreads();

    // ---- reduce Wv, Vv once (warp0) into Mc/Ci (dead) ----
    if (tid < 32) {
        const int j = tid;
        Mc[j] = (Wp[j] + Wp[32 + j]) + (Wp[64 + j] + Wp[96 + j]);   // Wv
        Ci[j] = (Vp[j] + Vp[32 + j]) + (Vp[64 + j] + Vp[96 + j]);   // Vv
    }
    __syncthreads();

    // ---- m = [mean_k Qm | w^T Dm | v^T Qm] (bank 4j+d, lanes distinct; Wv/Vv bcast) ----
    {
        const int d = tid;
        float m1 = 0.f, m2 = 0.f, m3 = 0.f;
        #pragma unroll
        for (int j = 0; j < KN; j++) {
            float dd = DQ[j * RP + d];
            float qq = DQ[(32 + j) * RP + d];
            m1 += qq;
            m2 += Mc[j] * dd;     // Wv
            m3 += Ci[j] * qq;     // Vv
        }
        sm[d]       = m1 * (1.0f / 32.0f);
        sm[128 + d] = m2;
        sm[256 + d] = m3;
    }
    __syncthreads();

    // ---- AvgPool1d(3,3) + residual (prefetched) ----
    {
        const int g = tid;
        float h = (sm[3 * g] + sm[3 * g + 1] + sm[3 * g + 2]) * (1.0f / 3.0f);
        out[node * DF + g] = res + h;
    }
}

extern "C" void kernel_launch(void* const* d_in, const int* in_sizes, int n_in,
                              void* d_out, int out_size)
{
    const float* feat = (const float*)d_in[0];
    const int*   sim  = (const int*)d_in[1];
    const int*   cor  = (const int*)d_in[2];
    float*       out  = (float*)d_out;

    const int n_nodes = in_sizes[1] / KN;    // 20000
    cudaFuncSetAttribute(coatt_mma, cudaFuncAttributeMaxDynamicSharedMemorySize, SMEM_BYTES);
    coatt_mma<<<n_nodes, 128, SMEM_BYTES>>>(feat, sim, cor, out);
}

// round 10
// speedup vs baseline: 2.7094x; 1.0915x over previous
#include <cuda_runtime.h>
#include <cstdint>

#define KN 32
#define DF 128
#define RP 132   // DQ row pad: 132 mod 32 = 4 -> conflict-free frag/m-phase maps, 16B rows
#define LP 36    // L row pad: float2/float4 aligned, col reads conflict-free

// smem floats: DQ 64*RP=8448 | L 32*LP=1152 | stats 384  -> 39936 B, 5 CTAs/SM
#define SMEM_FLOATS (64 * RP + KN * LP + 384)
#define SMEM_BYTES  (SMEM_FLOATS * 4)

// pack two f32 into bf16x2 (e0 -> low half, e1 -> high half)
__device__ __forceinline__ unsigned bfpack(float e0, float e1) {
    unsigned r; asm("cvt.rn.bf16x2.f32 %0, %1, %2;" : "=r"(r) : "f"(e1), "f"(e0)); return r;
}
// split f32 pair into (hi bf16x2, lo bf16x2)
__device__ __forceinline__ void bfsplit(float e0, float e1, unsigned& hi, unsigned& lo) {
    hi = bfpack(e0, e1);
    float h0 = __uint_as_float(hi << 16);
    float h1 = __uint_as_float(hi & 0xFFFF0000u);
    lo = bfpack(e0 - h0, e1 - h1);
}
__device__ __forceinline__ void mma16(float* c, const unsigned* a, const unsigned* b) {
    asm volatile("mma.sync.aligned.m16n8k16.row.col.f32.bf16.bf16.f32 "
        "{%0,%1,%2,%3}, {%4,%5,%6,%7}, {%8,%9}, {%0,%1,%2,%3};"
        : "+f"(c[0]), "+f"(c[1]), "+f"(c[2]), "+f"(c[3])
        : "r"(a[0]), "r"(a[1]), "r"(a[2]), "r"(a[3]), "r"(b[0]), "r"(b[1]));
}
__device__ __forceinline__ void cpa16(uint32_t dst, const float* src) {
    asm volatile("cp.async.cg.shared.global [%0], [%1], 16;" :: "r"(dst), "l"(src));
}

__global__ void __launch_bounds__(128, 5)
coatt_mma(const float* __restrict__ feat,
          const int* __restrict__ sim_idx,
          const int* __restrict__ cor_idx,
          float* __restrict__ out)
{
    extern __shared__ float sh[];
    float* DQ    = sh;                     // [64][RP] rows 0-31 Dm, 32-63 Qm
    float* L     = sh + 64 * RP;           // [32][LP] single L buffer
    float* stats = L + KN * LP;
    float* Mc = stats;                     // col max   -> later Wv
    float* Ci = stats + 32;                // 1/(32*colsum) -> later Pv
    float* Mr = stats + 64;                // row max   -> later Vv
    float* Rs = stats + 96;                // row sum
    float* Wp = stats + 128;               // [4][32] w partials
    float* Vp = stats + 256;               // [4][32] v partials
    float* sm = L;                         // alias: written after L dead

    const int tid  = threadIdx.x;
    const int q    = tid >> 5;
    const int lane = tid & 31;
    const int nh   = q >> 1;               // n-half: cols [16nh, 16nh+16)
    const int dh   = q & 1;                // d-half: d in [64dh, 64dh+64)
    const size_t node = blockIdx.x;

    // ---- early residual prefetch (hides tail LDG) ----
    const float res = __ldg(feat + node * DF + tid);

    // ---- neighbor indices via LDG + shfl ----
    int rowidx = 0;
    {
        const int gr = 16 * q + (lane & 15);
        if (lane < 16)
            rowidx = (gr < KN) ? __ldg(sim_idx + node * KN + gr)
                               : __ldg(cor_idx + node * KN + gr - KN);
    }

    // ---- gather via cp.async: warp q fills rows [16q,16q+16) ----
    {
        const int jg = lane >> 3;
        const int c8 = lane & 7;
        #pragma unroll
        for (int it = 0; it < 4; it++) {
            const int rloc = 4 * it + jg;
            const int ridx = __shfl_sync(0xffffffffu, rowidx, rloc);
            const int r    = 16 * q + rloc;
            const float* src = feat + (size_t)ridx * DF;
            uint32_t dst = (uint32_t)__cvta_generic_to_shared(DQ + r * RP);
            #pragma unroll
            for (int dc = 0; dc < 4; dc++) {
                const int c4 = dc * 8 + c8;
                cpa16(dst + 16 * c4, src + 4 * c4);
            }
        }
        asm volatile("cp.async.commit_group;");
        asm volatile("cp.async.wait_group 0;");
    }
    __syncthreads();

    // ---- L tile via split-bf16 3-term mma: warp q = (n-half nh, d-half dh) ----
    float C[2][2][4];
    #pragma unroll
    for (int mi = 0; mi < 2; mi++)
        #pragma unroll
        for (int ni = 0; ni < 2; ni++)
            #pragma unroll
            for (int e = 0; e < 4; e++) C[mi][ni][e] = 0.f;

    const int r8 = lane >> 2;              // 0..7
    const int c4 = lane & 3;               // 0..3
    #pragma unroll
    for (int kt = 0; kt < 4; kt++) {
        const int d0 = 64 * dh + 16 * kt;
        unsigned ah[2][4], al[2][4];
        #pragma unroll
        for (int mi = 0; mi < 2; mi++) {
            const float* base = DQ + (16 * mi + r8) * RP + d0 + 2 * c4;
            float2 p0 = *(const float2*)(base);
            float2 p1 = *(const float2*)(base + 8 * RP);
            float2 p2 = *(const float2*)(base + 8);
            float2 p3 = *(const float2*)(base + 8 * RP + 8);
            bfsplit(p0.x, p0.y, ah[mi][0], al[mi][0]);
            bfsplit(p1.x, p1.y, ah[mi][1], al[mi][1]);
            bfsplit(p2.x, p2.y, ah[mi][2], al[mi][2]);
            bfsplit(p3.x, p3.y, ah[mi][3], al[mi][3]);
        }
        unsigned bh[2][2], bl[2][2];
        #pragma unroll
        for (int ni = 0; ni < 2; ni++) {
            const float* base = DQ + (32 + 16 * nh + 8 * ni + r8) * RP + d0 + 2 * c4;
            float2 p0 = *(const float2*)(base);
            float2 p1 = *(const float2*)(base + 8);
            bfsplit(p0.x, p0.y, bh[ni][0], bl[ni][0]);
            bfsplit(p1.x, p1.y, bh[ni][1], bl[ni][1]);
        }
        #pragma unroll
        for (int mi = 0; mi < 2; mi++)
            #pragma unroll
            for (int ni = 0; ni < 2; ni++) {
                mma16(C[mi][ni], al[mi], bh[ni]);
                mma16(C[mi][ni], ah[mi], bl[ni]);
                mma16(C[mi][ni], ah[mi], bh[ni]);
            }
    }

    // ---- merge d-halves: dh0 stores, dh1 adds (disjoint n-halves concurrent) ----
    if (dh == 0) {
        #pragma unroll
        for (int mi = 0; mi < 2; mi++)
            #pragma unroll
            for (int ni = 0; ni < 2; ni++) {
                const int row = 16 * mi + r8;
                const int col = 16 * nh + 8 * ni + 2 * c4;
                *(float2*)(L + row * LP + col)       = make_float2(C[mi][ni][0], C[mi][ni][1]);
                *(float2*)(L + (row + 8) * LP + col) = make_float2(C[mi][ni][2], C[mi][ni][3]);
            }
    }
    __syncthreads();
    if (dh == 1) {
        #pragma unroll
        for (int mi = 0; mi < 2; mi++)
            #pragma unroll
            for (int ni = 0; ni < 2; ni++) {
                const int row = 16 * mi + r8;
                const int col = 16 * nh + 8 * ni + 2 * c4;
                float2 t0 = *(float2*)(L + row * LP + col);
                float2 t1 = *(float2*)(L + (row + 8) * LP + col);
                t0.x += C[mi][ni][0]; t0.y += C[mi][ni][1];
                t1.x += C[mi][ni][2]; t1.y += C[mi][ni][3];
                *(float2*)(L + row * LP + col)       = t0;
                *(float2*)(L + (row + 8) * LP + col) = t1;
            }
    }
    __syncthreads();

    // ---- stats: warp0 col max/sum (scalar, conflict-free), warp1 row (rotated float4) ----
    if (q == 0) {
        const int j = lane;
        float mc = -1e30f;
        #pragma unroll
        for (int k = 0; k < KN; k++) mc = fmaxf(mc, L[k * LP + j]);
        float cs = 0.f;
        #pragma unroll
        for (int k = 0; k < KN; k++) cs += __expf(L[k * LP + j] - mc);
        Mc[j] = mc;
        Ci[j] = 1.0f / (32.0f * cs);
    } else if (q == 1) {
        const int k = lane;
        const float* ra = L + k * LP;
        float mr = -1e30f;
        #pragma unroll
        for (int i = 0; i < 8; i++) {
            const int cc = 4 * ((i + (k >> 3)) & 7);
            float4 v = *(const float4*)(ra + cc);
            mr = fmaxf(mr, fmaxf(fmaxf(v.x, v.y), fmaxf(v.z, v.w)));
        }
        float rs = 0.f;
        #pragma unroll
        for (int i = 0; i < 8; i++) {
            const int cc = 4 * ((i + (k >> 3)) & 7);
            float4 v = *(const float4*)(ra + cc);
            rs += __expf(v.x - mr) + __expf(v.y - mr) + __expf(v.z - mr) + __expf(v.w - mr);
        }
        Mr[k] = mr;
        Rs[k] = rs;
    }
    __syncthreads();

    // ---- w partials: all 4 warps, rotated k-chunk (conflict-free rows) ----
    {
        const int j  = lane;
        const int k0 = 8 * ((q + (j >> 3)) & 3);
        const float* pa = L + j * LP + k0;
        float4 a0 = *(const float4*)pa;
        float4 a1 = *(const float4*)(pa + 4);
        float wj;
        wj  = __expf(a0.x - Mc[k0 + 0]) * Ci[k0 + 0];
        wj += __expf(a0.y - Mc[k0 + 1]) * Ci[k0 + 1];
        wj += __expf(a0.z - Mc[k0 + 2]) * Ci[k0 + 2];
        wj += __expf(a0.w - Mc[k0 + 3]) * Ci[k0 + 3];
        wj += __expf(a1.x - Mc[k0 + 4]) * Ci[k0 + 4];
        wj += __expf(a1.y - Mc[k0 + 5]) * Ci[k0 + 5];
        wj += __expf(a1.z - Mc[k0 + 6]) * Ci[k0 + 6];
        wj += __expf(a1.w - Mc[k0 + 7]) * Ci[k0 + 7];
        Wp[q * 32 + j] = wj;
    }
    __syncthreads();

    // ---- Wv/Pv reduce (warp0); Mc/Ci dead after w phase ----
    if (tid < 32) {
        const int j = tid;
        float wv = (Wp[j] + Wp[32 + j]) + (Wp[64 + j] + Wp[96 + j]);
        Mc[j] = wv;                        // Wv
        Ci[j] = __fdividef(wv, Rs[j]);     // Pv
    }
    __syncthreads();

    // ---- v partials: warp q, k in [8q,8q+8), column reads (conflict-free) ----
    {
        const int j = lane;
        float vj = 0.f;
        #pragma unroll
        for (int i = 0; i < 8; i++) {
            const int k = 8 * q + i;
            vj += Ci[k] * __expf(L[k * LP + j] - Mr[k]);
        }
        Vp[q * 32 + j] = vj;
    }
    __syncthreads();

    // ---- Vv reduce (warp0) into Mr (dead) ----
    if (tid < 32) {
        const int j = tid;
        Mr[j] = (Vp[j] + Vp[32 + j]) + (Vp[64 + j] + Vp[96 + j]);   // Vv
    }
    __syncthreads();

    // ---- m = [mean_k Qm | w^T Dm | v^T Qm] (bank 4j+d, lanes distinct) ----
    {
        const int d = tid;
        float m1 = 0.f, m2 = 0.f, m3 = 0.f;
        #pragma unroll
        for (int j = 0; j < KN; j++) {
            float dd = DQ[j * RP + d];
            float qq = DQ[(32 + j) * RP + d];
            m1 += qq;
            m2 += Mc[j] * dd;     // Wv
            m3 += Mr[j] * qq;     // Vv
        }
        sm[d]       = m1 * (1.0f / 32.0f);
        sm[128 + d] = m2;
        sm[256 + d] = m3;
    }
    __syncthreads();

    // ---- AvgPool1d(3,3) + residual (prefetched) ----
    {
        const int g = tid;
        float h = (sm[3 * g] + sm[3 * g + 1] + sm[3 * g + 2]) * (1.0f / 3.0f);
        out[node * DF + g] = res + h;
    }
}

extern "C" void kernel_launch(void* const* d_in, const int* in_sizes, int n_in,
                              void* d_out, int out_size)
{
    const float* feat = (const float*)d_in[0];
    const int*   sim  = (const int*)d_in[1];
    const int*   cor  = (const int*)d_in[2];
    float*       out  = (float*)d_out;

    const int n_nodes = in_sizes[1] / KN;    // 20000
    cudaFuncSetAttribute(coatt_mma, cudaFuncAttributeMaxDynamicSharedMemorySize, SMEM_BYTES);
    coatt_mma<<<n_nodes, 128, SMEM_BYTES>>>(feat, sim, cor, out);
}